// round 1
// baseline (speedup 1.0000x reference)
#include <cuda_runtime.h>
#include <math.h>

#define F_CNT 1024
#define HH 192
#define WW 192
#define NPIX (HH*WW)
#define FXc 200.0f
#define FYc 200.0f
#define CXc 96.0f
#define CYc 96.0f
#define EPSf 1e-8f
#define NLOSSBLK 432   // 3*NPIX / 256

// ---------------- device scratch (no allocations allowed) ----------------
__device__ float4 g_h1[F_CNT];    // mx, my, pA, pB   (power = (pA*dx+pB*dy)*dx + pC*dy*dy)
__device__ float  g_pC[F_CNT];
__device__ float4 g_cold[F_CNT];  // opv, r, g, b
__device__ float  g_key[F_CNT];   // Zc
__device__ float4 g_sh1[F_CNT];   // sorted copies
__device__ float  g_spC[F_CNT];
__device__ float4 g_scold[F_CNT];
__device__ float  g_partial[NLOSSBLK];

// ---------------- per-gaussian preprocess ----------------
__global__ void preprocess_kernel(const float* __restrict__ vp,
                                  const int*   __restrict__ faces,
                                  const float* __restrict__ qs,
                                  const float* __restrict__ ls,
                                  const float* __restrict__ lop)
{
    int f = blockIdx.x * blockDim.x + threadIdx.x;
    if (f >= F_CNT) return;

    int ia = faces[3*f+0], ib = faces[3*f+1], ic = faces[3*f+2];
    float ax = vp[3*ia], ay = vp[3*ia+1], az = vp[3*ia+2];
    float bx = vp[3*ib], by = vp[3*ib+1], bz = vp[3*ib+2];
    float cx = vp[3*ic], cy = vp[3*ic+1], cz = vp[3*ic+2];

    // centroid
    float tx = (ax+bx+cx)/3.0f, ty = (ay+by+cy)/3.0f, tz = (az+bz+cz)/3.0f;

    // face frame
    float e1x = bx-ax, e1y = by-ay, e1z = bz-az;
    float e2x = cx-ax, e2y = cy-ay, e2z = cz-az;
    float l1 = sqrtf(e1x*e1x + e1y*e1y + e1z*e1z);
    float i1 = 1.0f/(l1 + EPSf);
    float xx = e1x*i1, xy = e1y*i1, xz = e1z*i1;
    float nx = e1y*e2z - e1z*e2y;
    float ny = e1z*e2x - e1x*e2z;
    float nz = e1x*e2y - e1y*e2x;
    float ln = sqrtf(nx*nx + ny*ny + nz*nz);
    float in = 1.0f/(ln + EPSf);
    float zx = nx*in, zy = ny*in, zz = nz*in;
    // y = cross(z, x)
    float yx = zy*xz - zz*xy;
    float yy = zz*xx - zx*xz;
    float yz = zx*xy - zy*xx;

    // local gaussian rotation from quaternion (normalized)
    float qw = qs[4*f+0], qx = qs[4*f+1], qy = qs[4*f+2], qz = qs[4*f+3];
    float qn = sqrtf(qw*qw + qx*qx + qy*qy + qz*qz);
    float iq = 1.0f/(qn + EPSf);
    qw *= iq; qx *= iq; qy *= iq; qz *= iq;
    float R00 = 1.0f - 2.0f*(qy*qy + qz*qz), R01 = 2.0f*(qx*qy - qw*qz), R02 = 2.0f*(qx*qz + qw*qy);
    float R10 = 2.0f*(qx*qy + qw*qz), R11 = 1.0f - 2.0f*(qx*qx + qz*qz), R12 = 2.0f*(qy*qz - qw*qx);
    float R20 = 2.0f*(qx*qz - qw*qy), R21 = 2.0f*(qy*qz + qw*qx), R22 = 1.0f - 2.0f*(qx*qx + qy*qy);

    float s0 = expf(ls[3*f+0]), s1 = expf(ls[3*f+1]), s2 = expf(ls[3*f+2]);

    // G[i][j] = x_i*(R[j][0]*s0) + y_i*(R[j][1]*s1) + z_i*(R[j][2]*s2)
    float G[3][3];
    {
        float Rj0, Rj1, Rj2, w0, w1, w2;
        Rj0 = R00; Rj1 = R01; Rj2 = R02;
        w0 = Rj0*s0; w1 = Rj1*s1; w2 = Rj2*s2;
        G[0][0] = xx*w0 + yx*w1 + zx*w2;
        G[1][0] = xy*w0 + yy*w1 + zy*w2;
        G[2][0] = xz*w0 + yz*w1 + zz*w2;
        Rj0 = R10; Rj1 = R11; Rj2 = R12;
        w0 = Rj0*s0; w1 = Rj1*s1; w2 = Rj2*s2;
        G[0][1] = xx*w0 + yx*w1 + zx*w2;
        G[1][1] = xy*w0 + yy*w1 + zy*w2;
        G[2][1] = xz*w0 + yz*w1 + zz*w2;
        Rj0 = R20; Rj1 = R21; Rj2 = R22;
        w0 = Rj0*s0; w1 = Rj1*s1; w2 = Rj2*s2;
        G[0][2] = xx*w0 + yx*w1 + zx*w2;
        G[1][2] = xy*w0 + yy*w1 + zy*w2;
        G[2][2] = xz*w0 + yz*w1 + zz*w2;
    }

    // column norms -> global scales; normalized columns -> global_rot
    float gs[3], Gr[3][3];
    for (int j = 0; j < 3; j++) {
        gs[j] = sqrtf(G[0][j]*G[0][j] + G[1][j]*G[1][j] + G[2][j]*G[2][j]);
        float ig = 1.0f/(gs[j] + EPSf);
        Gr[0][j] = G[0][j]*ig; Gr[1][j] = G[1][j]*ig; Gr[2][j] = G[2][j]*ig;
    }

    // rot_to_quat
    float m00 = Gr[0][0], m11 = Gr[1][1], m22 = Gr[2][2];
    float pw = 0.5f*sqrtf(fmaxf(EPSf, 1.0f + m00 + m11 + m22));
    float px = 0.5f*sqrtf(fmaxf(EPSf, 1.0f + m00 - m11 - m22));
    float py = 0.5f*sqrtf(fmaxf(EPSf, 1.0f - m00 + m11 - m22));
    float pz = 0.5f*sqrtf(fmaxf(EPSf, 1.0f - m00 - m11 + m22));
    px = copysignf(px, Gr[2][1] - Gr[1][2]);
    py = copysignf(py, Gr[0][2] - Gr[2][0]);
    pz = copysignf(pz, Gr[1][0] - Gr[0][1]);

    // render's quat_to_rot (re-normalizes)
    float pn = sqrtf(pw*pw + px*px + py*py + pz*pz);
    float ip = 1.0f/(pn + EPSf);
    pw *= ip; px *= ip; py *= ip; pz *= ip;
    float N00 = 1.0f - 2.0f*(py*py + pz*pz), N01 = 2.0f*(px*py - pw*pz), N02 = 2.0f*(px*pz + pw*py);
    float N10 = 2.0f*(px*py + pw*pz), N11 = 1.0f - 2.0f*(px*px + pz*pz), N12 = 2.0f*(py*pz - pw*px);
    float N20 = 2.0f*(px*pz - pw*py), N21 = 2.0f*(py*pz + pw*px), N22 = 1.0f - 2.0f*(px*px + py*py);

    // M = Rn * diag-like column scale; cov3 = M M^T
    float M00 = N00*gs[0], M01 = N01*gs[1], M02 = N02*gs[2];
    float M10 = N10*gs[0], M11 = N11*gs[1], M12 = N12*gs[2];
    float M20 = N20*gs[0], M21 = N21*gs[1], M22 = N22*gs[2];
    float c300 = M00*M00 + M01*M01 + M02*M02;
    float c301 = M00*M10 + M01*M11 + M02*M12;
    float c302 = M00*M20 + M01*M21 + M02*M22;
    float c311 = M10*M10 + M11*M11 + M12*M12;
    float c312 = M10*M20 + M11*M21 + M12*M22;
    float c322 = M20*M20 + M21*M21 + M22*M22;

    // projection
    float X = tx, Y = ty, Z = tz;
    float valid = (Z > 0.2f) ? 1.0f : 0.0f;
    float Zc = fmaxf(Z, 0.2f);
    float mx = FXc*X/Zc + CXc;
    float my = FYc*Y/Zc + CYc;
    float j00 = FXc/Zc;
    float j02 = -FXc*X/(Zc*Zc);
    float j11 = FYc/Zc;
    float j12 = -FYc*Y/(Zc*Zc);

    float u0 = j00*c300 + j02*c302;
    float u1 = j00*c301 + j02*c312;
    float u2 = j00*c302 + j02*c322;
    float v1 = j11*c311 + j12*c312;
    float v2 = j11*c312 + j12*c322;
    float cA = u0*j00 + u2*j02 + 0.3f;
    float cB = u1*j11 + u2*j12;
    float cC = v1*j11 + v2*j12 + 0.3f;
    float det = fmaxf(cA*cC - cB*cB, EPSf);
    float invd = 1.0f/det;
    // conic: conA=cC/det, conB=-cB/det, conC=cA/det
    // power = -0.5*conA*dx^2 - 0.5*conC*dy^2 - conB*dx*dy
    float pA = -0.5f*cC*invd;
    float pB =  cB*invd;       // -conB
    float pC = -0.5f*cA*invd;

    float opv = expf(lop[f]) * valid;

    g_h1[f]  = make_float4(mx, my, pA, pB);
    g_pC[f]  = pC;
    g_key[f] = Zc;
    // colors filled by caller kernel arg? keep here: read colors directly
    g_cold[f].x = opv;   // r,g,b filled below in same kernel via extra ptr
}

// fill colors (separate tiny kernel to keep arg lists clean)
__global__ void colors_kernel(const float* __restrict__ cols)
{
    int f = blockIdx.x * blockDim.x + threadIdx.x;
    if (f >= F_CNT) return;
    float4 c = g_cold[f];
    c.y = cols[3*f+0];
    c.z = cols[3*f+1];
    c.w = cols[3*f+2];
    g_cold[f] = c;
}

// ---------------- stable bitonic sort by (Zc, idx) + reorder ----------------
__global__ void sort_kernel()
{
    __shared__ float key[F_CNT];
    __shared__ int   idx[F_CNT];
    int t = threadIdx.x;
    key[t] = g_key[t];
    idx[t] = t;
    __syncthreads();
    for (int k = 2; k <= F_CNT; k <<= 1) {
        for (int j = k >> 1; j > 0; j >>= 1) {
            int ixj = t ^ j;
            if (ixj > t) {
                float ka = key[t], kb = key[ixj];
                int   ea = idx[t], eb = idx[ixj];
                bool up = ((t & k) == 0);
                bool gt = (ka > kb) || (ka == kb && ea > eb);
                if (gt == up) {
                    key[t] = kb; key[ixj] = ka;
                    idx[t] = eb; idx[ixj] = ea;
                }
            }
            __syncthreads();
        }
    }
    int s = idx[t];
    g_sh1[t]   = g_h1[s];
    g_spC[t]   = g_pC[s];
    g_scold[t] = g_cold[s];
}

// ---------------- render: 16x16 pixel tiles, gaussians in smem ----------------
__global__ void __launch_bounds__(256) render_kernel(float* __restrict__ out)
{
    __shared__ float4 sh1[F_CNT];
    __shared__ float  spC[F_CNT];
    __shared__ float4 scold[F_CNT];
    int tid = threadIdx.y * 16 + threadIdx.x;
    for (int i = tid; i < F_CNT; i += 256) {
        sh1[i]   = g_sh1[i];
        spC[i]   = g_spC[i];
        scold[i] = g_scold[i];
    }
    __syncthreads();

    int x = blockIdx.x * 16 + threadIdx.x;
    int y = blockIdx.y * 16 + threadIdx.y;
    float fx = (float)x, fy = (float)y;

    float T = 1.0f, cr = 0.0f, cg = 0.0f, cb = 0.0f;
#pragma unroll 4
    for (int f = 0; f < F_CNT; f++) {
        float4 h = sh1[f];
        float dx = fx - h.x;
        float dy = fy - h.y;
        float p = fmaf(fmaf(h.w, dy, h.z * dx), dx, spC[f] * dy * dy);
        if (p > -18.0f) {                       // alpha < 1.6e-8 below: skip
            float4 c = scold[f];
            float al = fminf(c.x * __expf(fminf(p, 0.0f)), 0.99f);
            float w = al * T;
            cr = fmaf(w, c.y, cr);
            cg = fmaf(w, c.z, cg);
            cb = fmaf(w, c.w, cb);
            T *= (1.0f - al);
            if (T < 1e-6f) break;               // remaining contribution < 1e-6
        }
    }
    int pix = y * WW + x;
    out[pix]          = cr + T;   // 1 - sum(w) == prod(1-alpha) == T
    out[NPIX + pix]   = cg + T;
    out[2*NPIX + pix] = cb + T;
}

// ---------------- loss: deterministic two-stage reduction ----------------
__global__ void loss_partial_kernel(const float* __restrict__ out,
                                    const float* __restrict__ img,
                                    const float* __restrict__ mask)
{
    __shared__ float sd[256];
    int i = blockIdx.x * 256 + threadIdx.x;   // i < 3*NPIX exactly
    int p = i % NPIX;
    float m = mask[p];
    float target = 1.0f - m + img[i] * m;
    float d = out[i] - target;
    sd[threadIdx.x] = d * d;
    __syncthreads();
    for (int s = 128; s > 0; s >>= 1) {
        if (threadIdx.x < s) sd[threadIdx.x] += sd[threadIdx.x + s];
        __syncthreads();
    }
    if (threadIdx.x == 0) g_partial[blockIdx.x] = sd[0];
}

__global__ void loss_final_kernel(float* __restrict__ out)
{
    __shared__ float sd[512];
    int t = threadIdx.x;
    sd[t] = (t < NLOSSBLK) ? g_partial[t] : 0.0f;
    __syncthreads();
    for (int s = 256; s > 0; s >>= 1) {
        if (t < s) sd[t] += sd[t + s];
        __syncthreads();
    }
    if (t == 0) out[3 * NPIX] = sd[0] / (float)(3 * NPIX);
}

// ---------------- launch ----------------
extern "C" void kernel_launch(void* const* d_in, const int* in_sizes, int n_in,
                              void* d_out, int out_size)
{
    const float* img   = (const float*)d_in[0];
    const float* mask  = (const float*)d_in[1];
    const float* vp    = (const float*)d_in[2];
    const int*   faces = (const int*)  d_in[3];
    const float* qs    = (const float*)d_in[4];
    const float* ls    = (const float*)d_in[5];
    const float* cols  = (const float*)d_in[6];
    const float* lop   = (const float*)d_in[7];
    float* out = (float*)d_out;

    preprocess_kernel<<<4, 256>>>(vp, faces, qs, ls, lop);
    colors_kernel<<<4, 256>>>(cols);
    sort_kernel<<<1, F_CNT>>>();
    render_kernel<<<dim3(WW/16, HH/16), dim3(16, 16)>>>(out);
    loss_partial_kernel<<<NLOSSBLK, 256>>>(out, img, mask);
    loss_final_kernel<<<1, 512>>>(out);
}

// round 2
// speedup vs baseline: 1.0477x; 1.0477x over previous
#include <cuda_runtime.h>
#include <math.h>

#define F_CNT 1024
#define HH 192
#define WW 192
#define NPIX (HH*WW)
#define FXc 200.0f
#define FYc 200.0f
#define CXc 96.0f
#define CYc 96.0f
#define EPSf 1e-8f
#define NTILES 144   // 12x12 tiles of 16x16

// ---------------- device scratch (no allocations allowed) ----------------
__device__ float4 g_h1[F_CNT];    // mx, my, pA, pB   (power = (pA*dx+pB*dy)*dx + pC*dy*dy)
__device__ float  g_pC[F_CNT];
__device__ float4 g_cold[F_CNT];  // opv, r, g, b
__device__ float2 g_rxy[F_CNT];   // culling half-extents (rx<0 => invalid)
__device__ float  g_key[F_CNT];   // Zc
__device__ float4 g_sh1[F_CNT];   // sorted copies
__device__ float  g_spC[F_CNT];
__device__ float4 g_scold[F_CNT];
__device__ float2 g_srxy[F_CNT];
__device__ float  g_partial[NTILES];

// ---------------- per-gaussian preprocess ----------------
__global__ void preprocess_kernel(const float* __restrict__ vp,
                                  const int*   __restrict__ faces,
                                  const float* __restrict__ qs,
                                  const float* __restrict__ ls,
                                  const float* __restrict__ cols,
                                  const float* __restrict__ lop)
{
    int f = blockIdx.x * blockDim.x + threadIdx.x;
    if (f >= F_CNT) return;

    int ia = faces[3*f+0], ib = faces[3*f+1], ic = faces[3*f+2];
    float ax = vp[3*ia], ay = vp[3*ia+1], az = vp[3*ia+2];
    float bx = vp[3*ib], by = vp[3*ib+1], bz = vp[3*ib+2];
    float cx = vp[3*ic], cy = vp[3*ic+1], cz = vp[3*ic+2];

    float tx = (ax+bx+cx)/3.0f, ty = (ay+by+cy)/3.0f, tz = (az+bz+cz)/3.0f;

    float e1x = bx-ax, e1y = by-ay, e1z = bz-az;
    float e2x = cx-ax, e2y = cy-ay, e2z = cz-az;
    float l1 = sqrtf(e1x*e1x + e1y*e1y + e1z*e1z);
    float i1 = 1.0f/(l1 + EPSf);
    float xx = e1x*i1, xy = e1y*i1, xz = e1z*i1;
    float nx = e1y*e2z - e1z*e2y;
    float ny = e1z*e2x - e1x*e2z;
    float nz = e1x*e2y - e1y*e2x;
    float ln = sqrtf(nx*nx + ny*ny + nz*nz);
    float in = 1.0f/(ln + EPSf);
    float zx = nx*in, zy = ny*in, zz = nz*in;
    float yx = zy*xz - zz*xy;
    float yy = zz*xx - zx*xz;
    float yz = zx*xy - zy*xx;

    float qw = qs[4*f+0], qx = qs[4*f+1], qy = qs[4*f+2], qz = qs[4*f+3];
    float qn = sqrtf(qw*qw + qx*qx + qy*qy + qz*qz);
    float iq = 1.0f/(qn + EPSf);
    qw *= iq; qx *= iq; qy *= iq; qz *= iq;
    float R00 = 1.0f - 2.0f*(qy*qy + qz*qz), R01 = 2.0f*(qx*qy - qw*qz), R02 = 2.0f*(qx*qz + qw*qy);
    float R10 = 2.0f*(qx*qy + qw*qz), R11 = 1.0f - 2.0f*(qx*qx + qz*qz), R12 = 2.0f*(qy*qz - qw*qx);
    float R20 = 2.0f*(qx*qz - qw*qy), R21 = 2.0f*(qy*qz + qw*qx), R22 = 1.0f - 2.0f*(qx*qx + qy*qy);

    float s0 = expf(ls[3*f+0]), s1 = expf(ls[3*f+1]), s2 = expf(ls[3*f+2]);

    float G[3][3];
    {
        float w0, w1, w2;
        w0 = R00*s0; w1 = R01*s1; w2 = R02*s2;
        G[0][0] = xx*w0 + yx*w1 + zx*w2;
        G[1][0] = xy*w0 + yy*w1 + zy*w2;
        G[2][0] = xz*w0 + yz*w1 + zz*w2;
        w0 = R10*s0; w1 = R11*s1; w2 = R12*s2;
        G[0][1] = xx*w0 + yx*w1 + zx*w2;
        G[1][1] = xy*w0 + yy*w1 + zy*w2;
        G[2][1] = xz*w0 + yz*w1 + zz*w2;
        w0 = R20*s0; w1 = R21*s1; w2 = R22*s2;
        G[0][2] = xx*w0 + yx*w1 + zx*w2;
        G[1][2] = xy*w0 + yy*w1 + zy*w2;
        G[2][2] = xz*w0 + yz*w1 + zz*w2;
    }

    float gs[3], Gr[3][3];
    #pragma unroll
    for (int j = 0; j < 3; j++) {
        gs[j] = sqrtf(G[0][j]*G[0][j] + G[1][j]*G[1][j] + G[2][j]*G[2][j]);
        float ig = 1.0f/(gs[j] + EPSf);
        Gr[0][j] = G[0][j]*ig; Gr[1][j] = G[1][j]*ig; Gr[2][j] = G[2][j]*ig;
    }

    float m00 = Gr[0][0], m11 = Gr[1][1], m22 = Gr[2][2];
    float pw = 0.5f*sqrtf(fmaxf(EPSf, 1.0f + m00 + m11 + m22));
    float px = 0.5f*sqrtf(fmaxf(EPSf, 1.0f + m00 - m11 - m22));
    float py = 0.5f*sqrtf(fmaxf(EPSf, 1.0f - m00 + m11 - m22));
    float pz = 0.5f*sqrtf(fmaxf(EPSf, 1.0f - m00 - m11 + m22));
    px = copysignf(px, Gr[2][1] - Gr[1][2]);
    py = copysignf(py, Gr[0][2] - Gr[2][0]);
    pz = copysignf(pz, Gr[1][0] - Gr[0][1]);

    float pn = sqrtf(pw*pw + px*px + py*py + pz*pz);
    float ip = 1.0f/(pn + EPSf);
    pw *= ip; px *= ip; py *= ip; pz *= ip;
    float N00 = 1.0f - 2.0f*(py*py + pz*pz), N01 = 2.0f*(px*py - pw*pz), N02 = 2.0f*(px*pz + pw*py);
    float N10 = 2.0f*(px*py + pw*pz), N11 = 1.0f - 2.0f*(px*px + pz*pz), N12 = 2.0f*(py*pz - pw*px);
    float N20 = 2.0f*(px*pz - pw*py), N21 = 2.0f*(py*pz + pw*px), N22 = 1.0f - 2.0f*(px*px + py*py);

    float M00 = N00*gs[0], M01 = N01*gs[1], M02 = N02*gs[2];
    float M10 = N10*gs[0], M11 = N11*gs[1], M12 = N12*gs[2];
    float M20 = N20*gs[0], M21 = N21*gs[1], M22 = N22*gs[2];
    float c300 = M00*M00 + M01*M01 + M02*M02;
    float c301 = M00*M10 + M01*M11 + M02*M12;
    float c302 = M00*M20 + M01*M21 + M02*M22;
    float c311 = M10*M10 + M11*M11 + M12*M12;
    float c312 = M10*M20 + M11*M21 + M12*M22;
    float c322 = M20*M20 + M21*M21 + M22*M22;

    float X = tx, Y = ty, Z = tz;
    float valid = (Z > 0.2f) ? 1.0f : 0.0f;
    float Zc = fmaxf(Z, 0.2f);
    float mx = FXc*X/Zc + CXc;
    float my = FYc*Y/Zc + CYc;
    float j00 = FXc/Zc;
    float j02 = -FXc*X/(Zc*Zc);
    float j11 = FYc/Zc;
    float j12 = -FYc*Y/(Zc*Zc);

    float u0 = j00*c300 + j02*c302;
    float u1 = j00*c301 + j02*c312;
    float u2 = j00*c302 + j02*c322;
    float v1 = j11*c311 + j12*c312;
    float v2 = j11*c312 + j12*c322;
    float cA = u0*j00 + u2*j02 + 0.3f;
    float cB = u1*j11 + u2*j12;
    float cC = v1*j11 + v2*j12 + 0.3f;
    float det = fmaxf(cA*cC - cB*cB, EPSf);
    float invd = 1.0f/det;
    float pA = -0.5f*cC*invd;
    float pB =  cB*invd;
    float pCv = -0.5f*cA*invd;

    float opv = expf(lop[f]) * valid;

    // cull extents: boundary of p = -18 ellipse: max dx^2 = 36*cA, max dy^2 = 36*cC
    float rx = (valid > 0.0f) ? 6.0f*sqrtf(cA) : -1e9f;
    float ry = 6.0f*sqrtf(cC);

    g_h1[f]  = make_float4(mx, my, pA, pB);
    g_pC[f]  = pCv;
    g_key[f] = Zc;
    g_rxy[f] = make_float2(rx, ry);
    g_cold[f] = make_float4(opv, cols[3*f+0], cols[3*f+1], cols[3*f+2]);
}

// ---------------- stable bitonic sort by packed (Zc_bits, idx) + reorder ----------------
__global__ void sort_kernel()
{
    __shared__ unsigned long long key[F_CNT];
    int t = threadIdx.x;
    // Zc >= 0.2 > 0: positive float bit pattern is order-isomorphic as uint
    unsigned int kb = __float_as_uint(g_key[t]);
    key[t] = ((unsigned long long)kb << 32) | (unsigned int)t;
    __syncthreads();
    for (int k = 2; k <= F_CNT; k <<= 1) {
        for (int j = k >> 1; j > 0; j >>= 1) {
            int ixj = t ^ j;
            if (ixj > t) {
                unsigned long long ka = key[t], kbv = key[ixj];
                bool up = ((t & k) == 0);
                if ((ka > kbv) == up) { key[t] = kbv; key[ixj] = ka; }
            }
            __syncthreads();
        }
    }
    int s = (int)(key[t] & 0xffffffffu);
    g_sh1[t]   = g_h1[s];
    g_spC[t]   = g_pC[s];
    g_scold[t] = g_cold[s];
    g_srxy[t]  = g_rxy[s];
}

// ---------------- render: 16x16 tiles, per-tile culled list, fused loss partial ----------------
__global__ void __launch_bounds__(256) render_kernel(float* __restrict__ out,
                                                     const float* __restrict__ img,
                                                     const float* __restrict__ mask)
{
    __shared__ float4 sh1[F_CNT];
    __shared__ float  spC[F_CNT];
    __shared__ float4 scold[F_CNT];
    __shared__ unsigned short list[F_CNT];
    __shared__ int warp_off[8];
    __shared__ int s_total;
    __shared__ float red[256];

    int tid = threadIdx.y * 16 + threadIdx.x;
    for (int i = tid; i < F_CNT; i += 256) {
        sh1[i]   = g_sh1[i];
        spC[i]   = g_spC[i];
        scold[i] = g_scold[i];
    }
    __syncthreads();

    // ---- cull: thread tid tests gaussians [4*tid, 4*tid+4) against tile bbox ----
    float tx0 = (float)(blockIdx.x * 16), tx1 = tx0 + 15.0f;
    float ty0 = (float)(blockIdx.y * 16), ty1 = ty0 + 15.0f;
    int base = tid * 4;
    unsigned flags = 0; int cnt = 0;
#pragma unroll
    for (int k = 0; k < 4; k++) {
        int f = base + k;
        float4 h = sh1[f];
        float2 r = g_srxy[f];          // coalesced, read once
        bool ov = (h.x + r.x >= tx0) && (h.x - r.x <= tx1) &&
                  (h.y + r.y >= ty0) && (h.y - r.y <= ty1);
        if (ov) { flags |= (1u << k); cnt++; }
    }
    // order-preserving block scan (warp shuffle + serial warp-total scan)
    int lane = tid & 31, wid = tid >> 5;
    int incl = cnt;
#pragma unroll
    for (int o = 1; o < 32; o <<= 1) {
        int v = __shfl_up_sync(0xffffffffu, incl, o);
        if (lane >= o) incl += v;
    }
    if (lane == 31) warp_off[wid] = incl;
    __syncthreads();
    if (tid == 0) {
        int acc = 0;
#pragma unroll
        for (int w = 0; w < 8; w++) { int v = warp_off[w]; warp_off[w] = acc; acc += v; }
        s_total = acc;
    }
    __syncthreads();
    int offset = warp_off[wid] + incl - cnt;
#pragma unroll
    for (int k = 0; k < 4; k++)
        if (flags & (1u << k)) list[offset++] = (unsigned short)(base + k);
    __syncthreads();
    int total = s_total;

    // ---- composite over the culled, depth-ordered list ----
    int x = blockIdx.x * 16 + threadIdx.x;
    int y = blockIdx.y * 16 + threadIdx.y;
    float fx = (float)x, fy = (float)y;

    float T = 1.0f, cr = 0.0f, cg = 0.0f, cb = 0.0f;
#pragma unroll 2
    for (int i = 0; i < total; i++) {
        int f = list[i];
        float4 h = sh1[f];
        float dx = fx - h.x;
        float dy = fy - h.y;
        float p = fmaf(fmaf(h.w, dy, h.z * dx), dx, spC[f] * dy * dy);
        if (p > -18.0f) {
            float4 c = scold[f];
            float al = fminf(c.x * __expf(fminf(p, 0.0f)), 0.99f);
            float w = al * T;
            cr = fmaf(w, c.y, cr);
            cg = fmaf(w, c.z, cg);
            cb = fmaf(w, c.w, cb);
            T *= (1.0f - al);
        }
    }

    int pix = y * WW + x;
    float o0 = cr + T, o1 = cg + T, o2 = cb + T;   // 1 - sum(w) == prod(1-alpha) == T
    out[pix]          = o0;
    out[NPIX + pix]   = o1;
    out[2*NPIX + pix] = o2;

    // ---- fused loss partial (per tile) ----
    float m = mask[pix];
    float bt = 1.0f - m;
    float d0 = o0 - fmaf(img[pix],          m, bt);
    float d1 = o1 - fmaf(img[NPIX + pix],   m, bt);
    float d2 = o2 - fmaf(img[2*NPIX + pix], m, bt);
    red[tid] = fmaf(d0, d0, fmaf(d1, d1, d2*d2));
    __syncthreads();
#pragma unroll
    for (int s = 128; s > 0; s >>= 1) {
        if (tid < s) red[tid] += red[tid + s];
        __syncthreads();
    }
    if (tid == 0) g_partial[blockIdx.y * 12 + blockIdx.x] = red[0];
}

// ---------------- final loss reduction ----------------
__global__ void loss_final_kernel(float* __restrict__ out)
{
    __shared__ float sd[256];
    int t = threadIdx.x;
    sd[t] = (t < NTILES) ? g_partial[t] : 0.0f;
    __syncthreads();
#pragma unroll
    for (int s = 128; s > 0; s >>= 1) {
        if (t < s) sd[t] += sd[t + s];
        __syncthreads();
    }
    if (t == 0) out[3 * NPIX] = sd[0] / (float)(3 * NPIX);
}

// ---------------- launch ----------------
extern "C" void kernel_launch(void* const* d_in, const int* in_sizes, int n_in,
                              void* d_out, int out_size)
{
    const float* img   = (const float*)d_in[0];
    const float* mask  = (const float*)d_in[1];
    const float* vp    = (const float*)d_in[2];
    const int*   faces = (const int*)  d_in[3];
    const float* qs    = (const float*)d_in[4];
    const float* ls    = (const float*)d_in[5];
    const float* cols  = (const float*)d_in[6];
    const float* lop   = (const float*)d_in[7];
    float* out = (float*)d_out;

    preprocess_kernel<<<4, 256>>>(vp, faces, qs, ls, cols, lop);
    sort_kernel<<<1, F_CNT>>>();
    render_kernel<<<dim3(WW/16, HH/16), dim3(16, 16)>>>(out, img, mask);
    loss_final_kernel<<<1, 256>>>(out);
}

// round 3
// speedup vs baseline: 2.1718x; 2.0729x over previous
#include <cuda_runtime.h>
#include <math.h>

#define F_CNT 1024
#define HH 192
#define WW 192
#define NPIX (HH*WW)
#define FXc 200.0f
#define FYc 200.0f
#define CXc 96.0f
#define CYc 96.0f
#define EPSf 1e-8f
#define SEG 8
#define GSEG 128          // F_CNT / SEG
#define NCOMB 144         // NPIX / 256

// ---------------- device scratch (no allocations allowed) ----------------
__device__ float4 g_h1[F_CNT];     // mx, my, pA, pB
__device__ float  g_pC[F_CNT];
__device__ float4 g_cold[F_CNT];   // opv, r, g, b
__device__ float  g_key[F_CNT];    // Zc
__device__ float4 g_sh1[F_CNT];    // sorted copies
__device__ float  g_spC[F_CNT];
__device__ float4 g_scold[F_CNT];
__device__ float4 g_seg[SEG][NPIX];   // per-segment (T, r, g, b)
__device__ float  g_partial[NCOMB];

// ---------------- per-gaussian preprocess ----------------
__global__ void preprocess_kernel(const float* __restrict__ vp,
                                  const int*   __restrict__ faces,
                                  const float* __restrict__ qs,
                                  const float* __restrict__ ls,
                                  const float* __restrict__ cols,
                                  const float* __restrict__ lop)
{
    int f = blockIdx.x * blockDim.x + threadIdx.x;
    if (f >= F_CNT) return;

    int ia = faces[3*f+0], ib = faces[3*f+1], ic = faces[3*f+2];
    float ax = vp[3*ia], ay = vp[3*ia+1], az = vp[3*ia+2];
    float bx = vp[3*ib], by = vp[3*ib+1], bz = vp[3*ib+2];
    float cx = vp[3*ic], cy = vp[3*ic+1], cz = vp[3*ic+2];

    float tx = (ax+bx+cx)/3.0f, ty = (ay+by+cy)/3.0f, tz = (az+bz+cz)/3.0f;

    float e1x = bx-ax, e1y = by-ay, e1z = bz-az;
    float e2x = cx-ax, e2y = cy-ay, e2z = cz-az;
    float l1 = sqrtf(e1x*e1x + e1y*e1y + e1z*e1z);
    float i1 = 1.0f/(l1 + EPSf);
    float xx = e1x*i1, xy = e1y*i1, xz = e1z*i1;
    float nx = e1y*e2z - e1z*e2y;
    float ny = e1z*e2x - e1x*e2z;
    float nz = e1x*e2y - e1y*e2x;
    float ln = sqrtf(nx*nx + ny*ny + nz*nz);
    float in = 1.0f/(ln + EPSf);
    float zx = nx*in, zy = ny*in, zz = nz*in;
    float yx = zy*xz - zz*xy;
    float yy = zz*xx - zx*xz;
    float yz = zx*xy - zy*xx;

    float qw = qs[4*f+0], qx = qs[4*f+1], qy = qs[4*f+2], qz = qs[4*f+3];
    float qn = sqrtf(qw*qw + qx*qx + qy*qy + qz*qz);
    float iq = 1.0f/(qn + EPSf);
    qw *= iq; qx *= iq; qy *= iq; qz *= iq;
    float R00 = 1.0f - 2.0f*(qy*qy + qz*qz), R01 = 2.0f*(qx*qy - qw*qz), R02 = 2.0f*(qx*qz + qw*qy);
    float R10 = 2.0f*(qx*qy + qw*qz), R11 = 1.0f - 2.0f*(qx*qx + qz*qz), R12 = 2.0f*(qy*qz - qw*qx);
    float R20 = 2.0f*(qx*qz - qw*qy), R21 = 2.0f*(qy*qz + qw*qx), R22 = 1.0f - 2.0f*(qx*qx + qy*qy);

    float s0 = expf(ls[3*f+0]), s1 = expf(ls[3*f+1]), s2 = expf(ls[3*f+2]);

    float G[3][3];
    {
        float w0, w1, w2;
        w0 = R00*s0; w1 = R01*s1; w2 = R02*s2;
        G[0][0] = xx*w0 + yx*w1 + zx*w2;
        G[1][0] = xy*w0 + yy*w1 + zy*w2;
        G[2][0] = xz*w0 + yz*w1 + zz*w2;
        w0 = R10*s0; w1 = R11*s1; w2 = R12*s2;
        G[0][1] = xx*w0 + yx*w1 + zx*w2;
        G[1][1] = xy*w0 + yy*w1 + zy*w2;
        G[2][1] = xz*w0 + yz*w1 + zz*w2;
        w0 = R20*s0; w1 = R21*s1; w2 = R22*s2;
        G[0][2] = xx*w0 + yx*w1 + zx*w2;
        G[1][2] = xy*w0 + yy*w1 + zy*w2;
        G[2][2] = xz*w0 + yz*w1 + zz*w2;
    }

    float gs[3], Gr[3][3];
    #pragma unroll
    for (int j = 0; j < 3; j++) {
        gs[j] = sqrtf(G[0][j]*G[0][j] + G[1][j]*G[1][j] + G[2][j]*G[2][j]);
        float ig = 1.0f/(gs[j] + EPSf);
        Gr[0][j] = G[0][j]*ig; Gr[1][j] = G[1][j]*ig; Gr[2][j] = G[2][j]*ig;
    }

    float m00 = Gr[0][0], m11 = Gr[1][1], m22 = Gr[2][2];
    float pw = 0.5f*sqrtf(fmaxf(EPSf, 1.0f + m00 + m11 + m22));
    float px = 0.5f*sqrtf(fmaxf(EPSf, 1.0f + m00 - m11 - m22));
    float py = 0.5f*sqrtf(fmaxf(EPSf, 1.0f - m00 + m11 - m22));
    float pz = 0.5f*sqrtf(fmaxf(EPSf, 1.0f - m00 - m11 + m22));
    px = copysignf(px, Gr[2][1] - Gr[1][2]);
    py = copysignf(py, Gr[0][2] - Gr[2][0]);
    pz = copysignf(pz, Gr[1][0] - Gr[0][1]);

    float pn = sqrtf(pw*pw + px*px + py*py + pz*pz);
    float ip = 1.0f/(pn + EPSf);
    pw *= ip; px *= ip; py *= ip; pz *= ip;
    float N00 = 1.0f - 2.0f*(py*py + pz*pz), N01 = 2.0f*(px*py - pw*pz), N02 = 2.0f*(px*pz + pw*py);
    float N10 = 2.0f*(px*py + pw*pz), N11 = 1.0f - 2.0f*(px*px + pz*pz), N12 = 2.0f*(py*pz - pw*px);
    float N20 = 2.0f*(px*pz - pw*py), N21 = 2.0f*(py*pz + pw*px), N22 = 1.0f - 2.0f*(px*px + py*py);

    float M00 = N00*gs[0], M01 = N01*gs[1], M02 = N02*gs[2];
    float M10 = N10*gs[0], M11 = N11*gs[1], M12 = N12*gs[2];
    float M20 = N20*gs[0], M21 = N21*gs[1], M22 = N22*gs[2];
    float c300 = M00*M00 + M01*M01 + M02*M02;
    float c301 = M00*M10 + M01*M11 + M02*M12;
    float c302 = M00*M20 + M01*M21 + M02*M22;
    float c311 = M10*M10 + M11*M11 + M12*M12;
    float c312 = M10*M20 + M11*M21 + M12*M22;
    float c322 = M20*M20 + M21*M21 + M22*M22;

    float X = tx, Y = ty, Z = tz;
    float valid = (Z > 0.2f) ? 1.0f : 0.0f;
    float Zc = fmaxf(Z, 0.2f);
    float mx = FXc*X/Zc + CXc;
    float my = FYc*Y/Zc + CYc;
    float j00 = FXc/Zc;
    float j02 = -FXc*X/(Zc*Zc);
    float j11 = FYc/Zc;
    float j12 = -FYc*Y/(Zc*Zc);

    float u0 = j00*c300 + j02*c302;
    float u1 = j00*c301 + j02*c312;
    float u2 = j00*c302 + j02*c322;
    float v1 = j11*c311 + j12*c312;
    float v2 = j11*c312 + j12*c322;
    float cA = u0*j00 + u2*j02 + 0.3f;
    float cB = u1*j11 + u2*j12;
    float cC = v1*j11 + v2*j12 + 0.3f;
    float det = fmaxf(cA*cC - cB*cB, EPSf);
    float invd = 1.0f/det;
    float pA = -0.5f*cC*invd;
    float pB =  cB*invd;
    float pCv = -0.5f*cA*invd;

    float opv = expf(lop[f]) * valid;

    g_h1[f]  = make_float4(mx, my, pA, pB);
    g_pC[f]  = pCv;
    g_key[f] = Zc;
    g_cold[f] = make_float4(opv, cols[3*f+0], cols[3*f+1], cols[3*f+2]);
}

// ---------------- hybrid bitonic sort (key in register) + reorder ----------------
__global__ void __launch_bounds__(1024) sort_kernel()
{
    __shared__ unsigned long long sk[F_CNT];
    int t = threadIdx.x;
    // Zc >= 0.2 > 0: positive float bits are order-isomorphic as uint; idx in low
    // bits makes keys unique and the sort stable (matches jnp.argsort).
    unsigned long long key =
        ((unsigned long long)__float_as_uint(g_key[t]) << 32) | (unsigned int)t;

    #pragma unroll
    for (int k = 2; k <= F_CNT; k <<= 1) {
        bool dir = ((t & k) == 0);   // ascending block
        int j = k >> 1;
        for (; j >= 32; j >>= 1) {   // cross-warp: via smem
            sk[t] = key;
            __syncthreads();
            unsigned long long other = sk[t ^ j];
            bool takeMin = (dir == ((t & j) == 0));
            key = ((key < other) == takeMin) ? key : other;
            __syncthreads();
        }
        for (; j >= 1; j >>= 1) {    // intra-warp: shuffle
            unsigned long long other = __shfl_xor_sync(0xffffffffu, key, j);
            bool takeMin = (dir == ((t & j) == 0));
            key = ((key < other) == takeMin) ? key : other;
        }
    }

    int s = (int)(key & 0xffffffffu);
    g_sh1[t]   = g_h1[s];
    g_spC[t]   = g_pC[s];
    g_scold[t] = g_cold[s];
}

// ---------------- render one depth segment per block ----------------
__global__ void __launch_bounds__(256) render_seg_kernel()
{
    __shared__ float4 sh1[GSEG];
    __shared__ float  spC[GSEG];
    __shared__ float4 scold[GSEG];

    int tid = threadIdx.y * 16 + threadIdx.x;
    int segbase = blockIdx.z * GSEG;
    if (tid < GSEG) {
        sh1[tid] = g_sh1[segbase + tid];
        spC[tid] = g_spC[segbase + tid];
    } else {
        int i = tid - GSEG;
        scold[i] = g_scold[segbase + i];
    }
    __syncthreads();

    int x = blockIdx.x * 16 + threadIdx.x;
    int y = blockIdx.y * 16 + threadIdx.y;
    float fx = (float)x, fy = (float)y;

    float T = 1.0f, cr = 0.0f, cg = 0.0f, cb = 0.0f;
#pragma unroll 4
    for (int i = 0; i < GSEG; i++) {
        float4 h = sh1[i];
        float dx = fx - h.x;
        float dy = fy - h.y;
        float p = fmaf(fmaf(h.w, dy, h.z * dx), dx, spC[i] * dy * dy);
        if (p > -18.0f) {            // alpha < 1.6e-8 below: skip
            float4 c = scold[i];
            float al = fminf(c.x * __expf(fminf(p, 0.0f)), 0.99f);
            float w = al * T;
            cr = fmaf(w, c.y, cr);
            cg = fmaf(w, c.z, cg);
            cb = fmaf(w, c.w, cb);
            T *= (1.0f - al);
        }
    }
    g_seg[blockIdx.z][y * WW + x] = make_float4(T, cr, cg, cb);
}

// ---------------- combine segments in depth order + output + loss partial ----------------
__global__ void __launch_bounds__(256) combine_kernel(float* __restrict__ out,
                                                      const float* __restrict__ img,
                                                      const float* __restrict__ mask)
{
    __shared__ float red[256];
    int tid = threadIdx.x;
    int pix = blockIdx.x * 256 + tid;

    float T = 1.0f, cr = 0.0f, cg = 0.0f, cb = 0.0f;
#pragma unroll
    for (int s = 0; s < SEG; s++) {
        float4 v = g_seg[s][pix];
        cr = fmaf(T, v.y, cr);
        cg = fmaf(T, v.z, cg);
        cb = fmaf(T, v.w, cb);
        T *= v.x;
    }

    float o0 = cr + T, o1 = cg + T, o2 = cb + T;  // 1 - sum(w) == prod(1-alpha)
    out[pix]          = o0;
    out[NPIX + pix]   = o1;
    out[2*NPIX + pix] = o2;

    float m = mask[pix];
    float bt = 1.0f - m;
    float d0 = o0 - fmaf(img[pix],          m, bt);
    float d1 = o1 - fmaf(img[NPIX + pix],   m, bt);
    float d2 = o2 - fmaf(img[2*NPIX + pix], m, bt);
    red[tid] = fmaf(d0, d0, fmaf(d1, d1, d2*d2));
    __syncthreads();
#pragma unroll
    for (int s = 128; s > 0; s >>= 1) {
        if (tid < s) red[tid] += red[tid + s];
        __syncthreads();
    }
    if (tid == 0) g_partial[blockIdx.x] = red[0];
}

// ---------------- final loss reduction ----------------
__global__ void loss_final_kernel(float* __restrict__ out)
{
    __shared__ float sd[256];
    int t = threadIdx.x;
    sd[t] = (t < NCOMB) ? g_partial[t] : 0.0f;
    __syncthreads();
#pragma unroll
    for (int s = 128; s > 0; s >>= 1) {
        if (t < s) sd[t] += sd[t + s];
        __syncthreads();
    }
    if (t == 0) out[3 * NPIX] = sd[0] / (float)(3 * NPIX);
}

// ---------------- launch ----------------
extern "C" void kernel_launch(void* const* d_in, const int* in_sizes, int n_in,
                              void* d_out, int out_size)
{
    const float* img   = (const float*)d_in[0];
    const float* mask  = (const float*)d_in[1];
    const float* vp    = (const float*)d_in[2];
    const int*   faces = (const int*)  d_in[3];
    const float* qs    = (const float*)d_in[4];
    const float* ls    = (const float*)d_in[5];
    const float* cols  = (const float*)d_in[6];
    const float* lop   = (const float*)d_in[7];
    float* out = (float*)d_out;

    preprocess_kernel<<<4, 256>>>(vp, faces, qs, ls, cols, lop);
    sort_kernel<<<1, 1024>>>();
    render_seg_kernel<<<dim3(WW/16, HH/16, SEG), dim3(16, 16)>>>();
    combine_kernel<<<NCOMB, 256>>>(out, img, mask);
    loss_final_kernel<<<1, 256>>>(out);
}

// round 4
// speedup vs baseline: 2.1734x; 1.0008x over previous
#include <cuda_runtime.h>
#include <math.h>

#define F_CNT 1024
#define HH 192
#define WW 192
#define NPIX (HH*WW)
#define FXc 200.0f
#define FYc 200.0f
#define CXc 96.0f
#define CYc 96.0f
#define EPSf 1e-8f
#define SEG 8
#define GSEG 128                 // F_CNT / SEG
#define PIX_PER_BLK 128
#define NRBLK (NPIX / PIX_PER_BLK)   // 288

// ---------------- device scratch (no allocations allowed) ----------------
__device__ float4 g_sh1[F_CNT];    // sorted: mx, my, pA, pB
__device__ float  g_spC[F_CNT];
__device__ float4 g_scold[F_CNT];  // sorted: opv, r, g, b
__device__ float  g_partial[NRBLK];
__device__ int    g_count;         // zero-initialized; reset by last block each call

// ================= preprocess + stable sort, one block =================
__global__ void __launch_bounds__(1024) prep_sort_kernel(
        const float* __restrict__ vp,
        const int*   __restrict__ faces,
        const float* __restrict__ qs,
        const float* __restrict__ ls,
        const float* __restrict__ cols,
        const float* __restrict__ lop)
{
    __shared__ float4 h1s[F_CNT];
    __shared__ float  pCs[F_CNT];
    __shared__ float4 colds[F_CNT];
    __shared__ unsigned long long sk[F_CNT];

    int f = threadIdx.x;

    // ---------- preprocess gaussian f ----------
    int ia = faces[3*f+0], ib = faces[3*f+1], ic = faces[3*f+2];
    float ax = vp[3*ia], ay = vp[3*ia+1], az = vp[3*ia+2];
    float bx = vp[3*ib], by = vp[3*ib+1], bz = vp[3*ib+2];
    float cx = vp[3*ic], cy = vp[3*ic+1], cz = vp[3*ic+2];

    float tx = (ax+bx+cx)/3.0f, ty = (ay+by+cy)/3.0f, tz = (az+bz+cz)/3.0f;

    float e1x = bx-ax, e1y = by-ay, e1z = bz-az;
    float e2x = cx-ax, e2y = cy-ay, e2z = cz-az;
    float l1 = sqrtf(e1x*e1x + e1y*e1y + e1z*e1z);
    float i1 = 1.0f/(l1 + EPSf);
    float xx = e1x*i1, xy = e1y*i1, xz = e1z*i1;
    float nx = e1y*e2z - e1z*e2y;
    float ny = e1z*e2x - e1x*e2z;
    float nz = e1x*e2y - e1y*e2x;
    float ln = sqrtf(nx*nx + ny*ny + nz*nz);
    float in = 1.0f/(ln + EPSf);
    float zx = nx*in, zy = ny*in, zz = nz*in;
    float yx = zy*xz - zz*xy;
    float yy = zz*xx - zx*xz;
    float yz = zx*xy - zy*xx;

    float qw = qs[4*f+0], qx = qs[4*f+1], qy = qs[4*f+2], qz = qs[4*f+3];
    float qn = sqrtf(qw*qw + qx*qx + qy*qy + qz*qz);
    float iq = 1.0f/(qn + EPSf);
    qw *= iq; qx *= iq; qy *= iq; qz *= iq;
    float R00 = 1.0f - 2.0f*(qy*qy + qz*qz), R01 = 2.0f*(qx*qy - qw*qz), R02 = 2.0f*(qx*qz + qw*qy);
    float R10 = 2.0f*(qx*qy + qw*qz), R11 = 1.0f - 2.0f*(qx*qx + qz*qz), R12 = 2.0f*(qy*qz - qw*qx);
    float R20 = 2.0f*(qx*qz - qw*qy), R21 = 2.0f*(qy*qz + qw*qx), R22 = 1.0f - 2.0f*(qx*qx + qy*qy);

    float s0 = expf(ls[3*f+0]), s1 = expf(ls[3*f+1]), s2 = expf(ls[3*f+2]);

    float G[3][3];
    {
        float w0, w1, w2;
        w0 = R00*s0; w1 = R01*s1; w2 = R02*s2;
        G[0][0] = xx*w0 + yx*w1 + zx*w2;
        G[1][0] = xy*w0 + yy*w1 + zy*w2;
        G[2][0] = xz*w0 + yz*w1 + zz*w2;
        w0 = R10*s0; w1 = R11*s1; w2 = R12*s2;
        G[0][1] = xx*w0 + yx*w1 + zx*w2;
        G[1][1] = xy*w0 + yy*w1 + zy*w2;
        G[2][1] = xz*w0 + yz*w1 + zz*w2;
        w0 = R20*s0; w1 = R21*s1; w2 = R22*s2;
        G[0][2] = xx*w0 + yx*w1 + zx*w2;
        G[1][2] = xy*w0 + yy*w1 + zy*w2;
        G[2][2] = xz*w0 + yz*w1 + zz*w2;
    }

    float gs[3], Gr[3][3];
    #pragma unroll
    for (int j = 0; j < 3; j++) {
        gs[j] = sqrtf(G[0][j]*G[0][j] + G[1][j]*G[1][j] + G[2][j]*G[2][j]);
        float ig = 1.0f/(gs[j] + EPSf);
        Gr[0][j] = G[0][j]*ig; Gr[1][j] = G[1][j]*ig; Gr[2][j] = G[2][j]*ig;
    }

    float m00 = Gr[0][0], m11 = Gr[1][1], m22 = Gr[2][2];
    float pw = 0.5f*sqrtf(fmaxf(EPSf, 1.0f + m00 + m11 + m22));
    float px = 0.5f*sqrtf(fmaxf(EPSf, 1.0f + m00 - m11 - m22));
    float py = 0.5f*sqrtf(fmaxf(EPSf, 1.0f - m00 + m11 - m22));
    float pz = 0.5f*sqrtf(fmaxf(EPSf, 1.0f - m00 - m11 + m22));
    px = copysignf(px, Gr[2][1] - Gr[1][2]);
    py = copysignf(py, Gr[0][2] - Gr[2][0]);
    pz = copysignf(pz, Gr[1][0] - Gr[0][1]);

    float pn = sqrtf(pw*pw + px*px + py*py + pz*pz);
    float ip = 1.0f/(pn + EPSf);
    pw *= ip; px *= ip; py *= ip; pz *= ip;
    float N00 = 1.0f - 2.0f*(py*py + pz*pz), N01 = 2.0f*(px*py - pw*pz), N02 = 2.0f*(px*pz + pw*py);
    float N10 = 2.0f*(px*py + pw*pz), N11 = 1.0f - 2.0f*(px*px + pz*pz), N12 = 2.0f*(py*pz - pw*px);
    float N20 = 2.0f*(px*pz - pw*py), N21 = 2.0f*(py*pz + pw*px), N22 = 1.0f - 2.0f*(px*px + py*py);

    float M00 = N00*gs[0], M01 = N01*gs[1], M02 = N02*gs[2];
    float M10 = N10*gs[0], M11 = N11*gs[1], M12 = N12*gs[2];
    float M20 = N20*gs[0], M21 = N21*gs[1], M22 = N22*gs[2];
    float c300 = M00*M00 + M01*M01 + M02*M02;
    float c301 = M00*M10 + M01*M11 + M02*M12;
    float c302 = M00*M20 + M01*M21 + M02*M22;
    float c311 = M10*M10 + M11*M11 + M12*M12;
    float c312 = M10*M20 + M11*M21 + M12*M22;
    float c322 = M20*M20 + M21*M21 + M22*M22;

    float X = tx, Y = ty, Z = tz;
    float valid = (Z > 0.2f) ? 1.0f : 0.0f;
    float Zc = fmaxf(Z, 0.2f);
    float mx = FXc*X/Zc + CXc;
    float my = FYc*Y/Zc + CYc;
    float j00 = FXc/Zc;
    float j02 = -FXc*X/(Zc*Zc);
    float j11 = FYc/Zc;
    float j12 = -FYc*Y/(Zc*Zc);

    float u0 = j00*c300 + j02*c302;
    float u1 = j00*c301 + j02*c312;
    float u2 = j00*c302 + j02*c322;
    float v1 = j11*c311 + j12*c312;
    float v2 = j11*c312 + j12*c322;
    float cA = u0*j00 + u2*j02 + 0.3f;
    float cB = u1*j11 + u2*j12;
    float cC = v1*j11 + v2*j12 + 0.3f;
    float det = fmaxf(cA*cC - cB*cB, EPSf);
    float invd = 1.0f/det;

    h1s[f]   = make_float4(mx, my, -0.5f*cC*invd, cB*invd);
    pCs[f]   = -0.5f*cA*invd;
    colds[f] = make_float4(expf(lop[f]) * valid, cols[3*f+0], cols[3*f+1], cols[3*f+2]);

    // ---------- stable bitonic sort on (Zc_bits << 32 | idx) ----------
    // Zc >= 0.2 > 0: positive float bits are order-isomorphic as uint.
    int t = f;
    unsigned long long key =
        ((unsigned long long)__float_as_uint(Zc) << 32) | (unsigned int)t;
    __syncthreads();   // attrs staged; also pre-sort barrier

    #pragma unroll
    for (int k = 2; k <= F_CNT; k <<= 1) {
        bool dir = ((t & k) == 0);
        int j = k >> 1;
        for (; j >= 32; j >>= 1) {           // cross-warp via smem
            sk[t] = key;
            __syncthreads();
            unsigned long long other = sk[t ^ j];
            bool takeMin = (dir == ((t & j) == 0));
            key = ((key < other) == takeMin) ? key : other;
            __syncthreads();
        }
        for (; j >= 1; j >>= 1) {            // intra-warp via shuffle
            unsigned long long other = __shfl_xor_sync(0xffffffffu, key, j);
            bool takeMin = (dir == ((t & j) == 0));
            key = ((key < other) == takeMin) ? key : other;
        }
    }

    int s = (int)(key & 0xffffffffu);
    g_sh1[t]   = h1s[s];
    g_spC[t]   = pCs[s];
    g_scold[t] = colds[s];
}

// ============ fused render (per-segment) + combine + loss ============
// block = 1024 threads = 128 pixels x 8 depth segments.
__global__ void __launch_bounds__(1024, 2) render_fused_kernel(
        float* __restrict__ out,
        const float* __restrict__ img,
        const float* __restrict__ mask)
{
    __shared__ float4 sh1[F_CNT];
    __shared__ float  spC[F_CNT];
    __shared__ float4 scold[F_CNT];
    __shared__ float4 comb[SEG][PIX_PER_BLK];
    __shared__ float  red[PIX_PER_BLK];
    __shared__ int    s_last;

    int tid = threadIdx.x;
    sh1[tid]   = g_sh1[tid];
    spC[tid]   = g_spC[tid];
    scold[tid] = g_scold[tid];
    __syncthreads();

    int pl  = tid & (PIX_PER_BLK - 1);   // pixel-local
    int seg = tid >> 7;                  // segment
    int pix = blockIdx.x * PIX_PER_BLK + pl;
    float fx = (float)(pix % WW), fy = (float)(pix / WW);

    int base = seg * GSEG;
    float T = 1.0f, cr = 0.0f, cg = 0.0f, cb = 0.0f;
#pragma unroll 4
    for (int i = base; i < base + GSEG; i++) {
        float4 h = sh1[i];
        float dx = fx - h.x;
        float dy = fy - h.y;
        float p = fmaf(fmaf(h.w, dy, h.z * dx), dx, spC[i] * dy * dy);
        if (p > -18.0f) {                 // alpha < 1.6e-8 below: skip
            float4 c = scold[i];
            float al = fminf(c.x * __expf(fminf(p, 0.0f)), 0.99f);
            float w = al * T;
            cr = fmaf(w, c.y, cr);
            cg = fmaf(w, c.z, cg);
            cb = fmaf(w, c.w, cb);
            T *= (1.0f - al);
        }
    }
    comb[seg][pl] = make_float4(T, cr, cg, cb);
    __syncthreads();

    // ---- per-pixel ordered fold of 8 segments (threads 0..127) ----
    if (tid < PIX_PER_BLK) {
        float Tt = 1.0f, r = 0.0f, g = 0.0f, b = 0.0f;
#pragma unroll
        for (int s = 0; s < SEG; s++) {
            float4 v = comb[s][tid];
            r = fmaf(Tt, v.y, r);
            g = fmaf(Tt, v.z, g);
            b = fmaf(Tt, v.w, b);
            Tt *= v.x;
        }
        float o0 = r + Tt, o1 = g + Tt, o2 = b + Tt;  // 1 - sum(w) == prod(1-alpha)
        int p = blockIdx.x * PIX_PER_BLK + tid;
        out[p]          = o0;
        out[NPIX + p]   = o1;
        out[2*NPIX + p] = o2;

        float m  = mask[p];
        float bt = 1.0f - m;
        float d0 = o0 - fmaf(img[p],          m, bt);
        float d1 = o1 - fmaf(img[NPIX + p],   m, bt);
        float d2 = o2 - fmaf(img[2*NPIX + p], m, bt);
        red[tid] = fmaf(d0, d0, fmaf(d1, d1, d2*d2));
    }
    __syncthreads();
#pragma unroll
    for (int s = 64; s > 0; s >>= 1) {
        if (tid < s) red[tid] += red[tid + s];
        __syncthreads();
    }

    // ---- last block finishes the loss (deterministic fixed-order sum) ----
    if (tid == 0) {
        g_partial[blockIdx.x] = red[0];
        __threadfence();
        int ticket = atomicAdd(&g_count, 1);
        s_last = (ticket == NRBLK - 1);
    }
    __syncthreads();
    if (s_last && tid < 32) {
        __threadfence();
        float a = 0.0f;
        for (int i = tid; i < NRBLK; i += 32) {
            float v = *((volatile float*)&g_partial[i]);
            a += v;
        }
#pragma unroll
        for (int o = 16; o > 0; o >>= 1)
            a += __shfl_down_sync(0xffffffffu, a, o);
        if (tid == 0) {
            out[3 * NPIX] = a / (float)(3 * NPIX);
            g_count = 0;   // reset for next graph replay
        }
    }
}

// ---------------- launch ----------------
extern "C" void kernel_launch(void* const* d_in, const int* in_sizes, int n_in,
                              void* d_out, int out_size)
{
    const float* img   = (const float*)d_in[0];
    const float* mask  = (const float*)d_in[1];
    const float* vp    = (const float*)d_in[2];
    const int*   faces = (const int*)  d_in[3];
    const float* qs    = (const float*)d_in[4];
    const float* ls    = (const float*)d_in[5];
    const float* cols  = (const float*)d_in[6];
    const float* lop   = (const float*)d_in[7];
    float* out = (float*)d_out;

    prep_sort_kernel<<<1, 1024>>>(vp, faces, qs, ls, cols, lop);
    render_fused_kernel<<<NRBLK, 1024>>>(out, img, mask);
}